// round 1
// baseline (speedup 1.0000x reference)
#include <cuda_runtime.h>
#include <cstdint>
#include <cstddef>

// Problem constants
#define T_TOT 8192       // B*N tokens
#define MULT  512        // multiplicity
#define OUTW  8192       // output row width (512*16)
#define VROW  1536       // vectors row width (512*3)

// GEMM tiling
#define BT 64
#define BW 128
#define BK 32

__device__ __forceinline__ uint32_t f2tf(float x) {
    uint32_t r;
    asm("cvt.rna.tf32.f32 %0, %1;" : "=r"(r) : "f"(x));
    return r;
}

__device__ __forceinline__ void mma8(float* c, const uint32_t* a, const uint32_t* b) {
    asm volatile(
        "mma.sync.aligned.m16n8k8.row.col.f32.tf32.tf32.f32 "
        "{%0,%1,%2,%3},{%4,%5,%6,%7},{%8,%9},{%0,%1,%2,%3};\n"
        : "+f"(c[0]), "+f"(c[1]), "+f"(c[2]), "+f"(c[3])
        : "r"(a[0]), "r"(a[1]), "r"(a[2]), "r"(a[3]),
          "r"(b[0]), "r"(b[1]));
}

// out1[t, w, i] = (1/sqrt(512)) * sum_u v[t,u,i] * W1[u,w]
// Output col for (w,i): 512 + w*3 + i
__global__ void __launch_bounds__(256, 1)
gemm1(const float* __restrict__ V, const float* __restrict__ W1,
      float* __restrict__ out) {
    __shared__ uint32_t sV[3][BT][BK + 1];   // tf32 bits, A operand per component i
    __shared__ uint32_t sW[BK][BW + 8];      // tf32 bits, B operand (stride 136 -> conflict-free frag loads)

    const int tt0 = blockIdx.y * BT;
    const int w0  = blockIdx.x * BW;
    const int tid = threadIdx.x;
    const int lane = tid & 31;
    const int wid  = tid >> 5;
    const int warp_t = wid >> 2;   // 0..1
    const int warp_w = wid & 3;    // 0..3

    float acc[3][2][4][4];
#pragma unroll
    for (int i = 0; i < 3; i++)
#pragma unroll
        for (int mt = 0; mt < 2; mt++)
#pragma unroll
            for (int nt = 0; nt < 4; nt++)
#pragma unroll
                for (int r = 0; r < 4; r++)
                    acc[i][mt][nt][r] = 0.0f;

    for (int k0 = 0; k0 < MULT; k0 += BK) {
        // ---- load V chunk: 64 rows x (32 u x 3 i) = 64 x 96 floats, scatter to sV[i][t][u]
        for (int l = tid; l < BT * 24; l += 256) {
            const int t = l / 24;
            const int q = l - t * 24;
            const float4 d = *reinterpret_cast<const float4*>(
                V + (size_t)(tt0 + t) * VROW + (size_t)k0 * 3 + q * 4);
            const int e = q * 4;
            sV[(e + 0) % 3][t][(e + 0) / 3] = f2tf(d.x);
            sV[(e + 1) % 3][t][(e + 1) / 3] = f2tf(d.y);
            sV[(e + 2) % 3][t][(e + 2) / 3] = f2tf(d.z);
            sV[(e + 3) % 3][t][(e + 3) / 3] = f2tf(d.w);
        }
        // ---- load W1 chunk: 32 u-rows x 128 w
        for (int l = tid; l < BK * 32; l += 256) {
            const int u  = l / 32;
            const int qw = l - u * 32;
            const float4 d = *reinterpret_cast<const float4*>(
                W1 + (size_t)(k0 + u) * MULT + w0 + qw * 4);
            sW[u][qw * 4 + 0] = f2tf(d.x);
            sW[u][qw * 4 + 1] = f2tf(d.y);
            sW[u][qw * 4 + 2] = f2tf(d.z);
            sW[u][qw * 4 + 3] = f2tf(d.w);
        }
        __syncthreads();

#pragma unroll
        for (int kk = 0; kk < BK; kk += 8) {
            uint32_t b[4][2];
#pragma unroll
            for (int nt = 0; nt < 4; nt++) {
                const int n = warp_w * 32 + nt * 8 + (lane >> 2);
                b[nt][0] = sW[kk + (lane & 3)][n];
                b[nt][1] = sW[kk + 4 + (lane & 3)][n];
            }
#pragma unroll
            for (int i = 0; i < 3; i++) {
                uint32_t a[2][4];
#pragma unroll
                for (int mt = 0; mt < 2; mt++) {
                    const int r = warp_t * 32 + mt * 16 + (lane >> 2);
                    a[mt][0] = sV[i][r][kk + (lane & 3)];
                    a[mt][1] = sV[i][r + 8][kk + (lane & 3)];
                    a[mt][2] = sV[i][r][kk + 4 + (lane & 3)];
                    a[mt][3] = sV[i][r + 8][kk + 4 + (lane & 3)];
                }
#pragma unroll
                for (int mt = 0; mt < 2; mt++)
#pragma unroll
                    for (int nt = 0; nt < 4; nt++)
                        mma8(acc[i][mt][nt], a[mt], b[nt]);
            }
        }
        __syncthreads();
    }

    // ---- epilogue: scale and store to interleaved layout
    const float sc = 0.04419417382415922f;  // 1/sqrt(512)
#pragma unroll
    for (int i = 0; i < 3; i++)
#pragma unroll
        for (int mt = 0; mt < 2; mt++)
#pragma unroll
            for (int nt = 0; nt < 4; nt++) {
                const int r = tt0 + warp_t * 32 + mt * 16 + (lane >> 2);
                const int w = w0 + warp_w * 32 + nt * 8 + (lane & 3) * 2;
                float* p = out + (size_t)r * OUTW + 512 + (size_t)w * 3 + i;
                p[0] = acc[i][mt][nt][0] * sc;
                p[3] = acc[i][mt][nt][1] * sc;          // col w+1 -> +3 floats
                float* p2 = p + (size_t)8 * OUTW;       // row r+8
                p2[0] = acc[i][mt][nt][2] * sc;
                p2[3] = acc[i][mt][nt][3] * sc;
            }
}

// out0 (cols [0,512)) and the exact-zero cols [2048,8192), one float4 per thread.
__global__ void __launch_bounds__(256)
fill01(const float* __restrict__ S, const float* __restrict__ W0,
       float4* __restrict__ out4) {
    const int QPR = 1664;  // 128 quads out0 + 1536 quads zeros per row
    const int idx = blockIdx.x * blockDim.x + threadIdx.x;
    if (idx >= T_TOT * QPR) return;
    const int row = idx / QPR;
    const int q   = idx - row * QPR;
    if (q < 128) {
        const int w = q * 4;
        const float s0 = S[row * 3 + 0];
        const float s1 = S[row * 3 + 1];
        const float s2 = S[row * 3 + 2];
        const float k = 0.5773502691896258f;  // 1/sqrt(3)
        float4 v;
        v.x = (s0 * W0[w + 0] + s1 * W0[512 + w + 0] + s2 * W0[1024 + w + 0]) * k;
        v.y = (s0 * W0[w + 1] + s1 * W0[512 + w + 1] + s2 * W0[1024 + w + 1]) * k;
        v.z = (s0 * W0[w + 2] + s1 * W0[512 + w + 2] + s2 * W0[1024 + w + 2]) * k;
        v.w = (s0 * W0[w + 3] + s1 * W0[512 + w + 3] + s2 * W0[1024 + w + 3]) * k;
        out4[(size_t)row * 2048 + q] = v;
    } else {
        // zero quads: col quad index 512 + (q - 128)
        out4[(size_t)row * 2048 + (size_t)q + 384] = make_float4(0.f, 0.f, 0.f, 0.f);
    }
}

extern "C" void kernel_launch(void* const* d_in, const int* in_sizes, int n_in,
                              void* d_out, int out_size) {
    const float* V  = nullptr;   // vectors [4,2048,1536] = 12582912
    const float* S  = nullptr;   // scalars [4,2048,3]    = 24576
    const float* W0 = nullptr;   // [3,512]               = 1536
    const float* W1 = nullptr;   // [512,512]             = 262144
    for (int i = 0; i < n_in; i++) {
        switch (in_sizes[i]) {
            case 12582912: V  = (const float*)d_in[i]; break;
            case 24576:    S  = (const float*)d_in[i]; break;
            case 1536:     W0 = (const float*)d_in[i]; break;
            case 262144:   W1 = (const float*)d_in[i]; break;
            default: break;
        }
    }
    float* out = (float*)d_out;

    // out0 + zero block (independent of gemm region)
    {
        const int total = T_TOT * 1664;
        fill01<<<(total + 255) / 256, 256>>>(S, W0, (float4*)out);
    }
    // out1 (1o -> 1o path), 3 components
    {
        dim3 grid(MULT / BW, T_TOT / BT);  // (4, 128)
        gemm1<<<grid, 256>>>(V, W1, out);
    }
}

// round 2
// speedup vs baseline: 1.3830x; 1.3830x over previous
#include <cuda_runtime.h>
#include <cstdint>
#include <cstddef>

// Problem constants
#define T_TOT 8192
#define MULT  512
#define OUTW  8192
#define VROW  1536

// Tiling
#define BT 64
#define BW 128
#define BK 32
#define NTHR 512
#define PV 40                 // padded k-extent per sV row (conflict-free LDS.64)
#define PW 40
#define SV_I (BT*PV)          // 2560 u32 per component
#define SV_STAGE (3*SV_I)     // 7680 u32
#define SW_STAGE (BW*PW)      // 5120 u32
#define SMEM_U32 (2*SV_STAGE + 2*SW_STAGE + 256 + 384)
#define SMEM_BYTES (SMEM_U32*4)

__device__ __forceinline__ uint32_t f2tf(float x) {
    uint32_t r;
    asm("cvt.rna.tf32.f32 %0, %1;" : "=r"(r) : "f"(x));
    return r;
}
// k in [0,32): k = 8g + 4h + c  ->  8g + 2c + h  (pairs (k, k+4) adjacent)
__device__ __forceinline__ int kperm(int u) {
    return 8 * (u >> 3) + 2 * (u & 3) + ((u >> 2) & 1);
}

__device__ __forceinline__ void mma8(float* c, const uint32_t* a, const uint32_t* b) {
    asm volatile(
        "mma.sync.aligned.m16n8k8.row.col.f32.tf32.tf32.f32 "
        "{%0,%1,%2,%3},{%4,%5,%6,%7},{%8,%9},{%0,%1,%2,%3};\n"
        : "+f"(c[0]), "+f"(c[1]), "+f"(c[2]), "+f"(c[3])
        : "r"(a[0]), "r"(a[1]), "r"(a[2]), "r"(a[3]),
          "r"(b[0]), "r"(b[1]));
}

__global__ void __launch_bounds__(NTHR, 1)
fused(const float* __restrict__ V, const float* __restrict__ W1,
      const float* __restrict__ S, const float* __restrict__ W0,
      float* __restrict__ out)
{
    extern __shared__ uint32_t dsm[];
    uint32_t* sV  = dsm;                         // 2 * SV_STAGE
    uint32_t* sW  = dsm + 2 * SV_STAGE;          // 2 * SW_STAGE
    float*    sS  = (float*)(dsm + 2 * SV_STAGE + 2 * SW_STAGE);  // 64*4
    float*    sW0 = sS + 256;                    // 3*128

    const int tid  = threadIdx.x;
    const int lane = tid & 31;
    const int wid  = tid >> 5;
    const int warp_t = wid >> 2;   // 0..3 -> rows warp_t*16
    const int warp_w = wid & 3;    // 0..3 -> cols warp_w*32
    const int bx = blockIdx.x, by = blockIdx.y;
    const int tt0 = by * BT, w0 = bx * BW;

    // ---- prologue small loads (visible after first __syncthreads in loop)
    if (tid < 192) sS[(tid / 3) * 4 + (tid % 3)] = S[(size_t)(tt0 + tid / 3) * 3 + (tid % 3)];
    if (tid < 384) { int c = tid >> 7, j = tid & 127; sW0[c * 128 + j] = W0[c * 512 + w0 + j]; }

    // ---- precompute staging addresses (loop-invariant)
    const float* vptr[3]; int voff[3][4];
#pragma unroll
    for (int s = 0; s < 3; s++) {
        int l = tid + s * NTHR;          // 0..1535
        int t = l / 24, q = l % 24;
        vptr[s] = V + (size_t)(tt0 + t) * VROW + 4 * q;
#pragma unroll
        for (int j = 0; j < 4; j++) {
            int e = 4 * q + j, i = e % 3, u = e / 3;
            voff[s][j] = i * SV_I + t * PV + kperm(u);
        }
    }
    const float* wptr[2]; int woff[2][4];
#pragma unroll
    for (int s = 0; s < 2; s++) {
        int l = tid + s * NTHR;          // 0..1023
        int u = l >> 5, qw = l & 31;
        wptr[s] = W1 + (size_t)u * MULT + w0 + 4 * qw;
#pragma unroll
        for (int j = 0; j < 4; j++) woff[s][j] = (4 * qw + j) * PW + kperm(u);
    }

    float acc[3][4][4];
#pragma unroll
    for (int i = 0; i < 3; i++)
#pragma unroll
        for (int n = 0; n < 4; n++)
#pragma unroll
            for (int r = 0; r < 4; r++) acc[i][n][r] = 0.f;

    // ---- first global fetch (k0 = 0)
    float4 vreg[3], wreg[2];
#pragma unroll
    for (int s = 0; s < 3; s++) vreg[s] = *reinterpret_cast<const float4*>(vptr[s]);
#pragma unroll
    for (int s = 0; s < 2; s++) wreg[s] = *reinterpret_cast<const float4*>(wptr[s]);

    float4* out4 = reinterpret_cast<float4*>(out);
    const float4 zq4 = make_float4(0.f, 0.f, 0.f, 0.f);

    for (int it = 0; it < 16; ++it) {
        const int sbV = (it & 1) * SV_STAGE;
        const int sbW = (it & 1) * SW_STAGE;

        // ---- store staged regs -> smem (tf32 convert + k-perm scatter)
#pragma unroll
        for (int s = 0; s < 3; s++) {
            sV[sbV + voff[s][0]] = f2tf(vreg[s].x);
            sV[sbV + voff[s][1]] = f2tf(vreg[s].y);
            sV[sbV + voff[s][2]] = f2tf(vreg[s].z);
            sV[sbV + voff[s][3]] = f2tf(vreg[s].w);
        }
#pragma unroll
        for (int s = 0; s < 2; s++) {
            sW[sbW + woff[s][0]] = f2tf(wreg[s].x);
            sW[sbW + woff[s][1]] = f2tf(wreg[s].y);
            sW[sbW + woff[s][2]] = f2tf(wreg[s].z);
            sW[sbW + woff[s][3]] = f2tf(wreg[s].w);
        }
        __syncthreads();

        // ---- prefetch next K chunk
        if (it < 15) {
#pragma unroll
            for (int s = 0; s < 3; s++) { vptr[s] += 96;        vreg[s] = *reinterpret_cast<const float4*>(vptr[s]); }
#pragma unroll
            for (int s = 0; s < 2; s++) { wptr[s] += 32 * MULT; wreg[s] = *reinterpret_cast<const float4*>(wptr[s]); }
        }

        // ---- stream out the exact-zero block (overlaps with MMA, DRAM is idle)
        {
            int z  = it * 1536 + tid * 3;           // quad index within CTA zero-block
            int zr = z / 384, zc = z % 384;         // 384 quads per row, stays in-row
            float4* zp = out4 + (size_t)(tt0 + zr) * 2048 + 512 + 384 * bx + zc;
            zp[0] = zq4; zp[1] = zq4; zp[2] = zq4;
        }

        // ---- compute 4 k8-steps from smem
#pragma unroll
        for (int g = 0; g < 4; g++) {
            uint32_t b[4][2];
#pragma unroll
            for (int nt = 0; nt < 4; nt++) {
                int n = warp_w * 32 + nt * 8 + (lane >> 2);
                const uint2 bb = *reinterpret_cast<const uint2*>(
                    &sW[sbW + n * PW + 8 * g + 2 * (lane & 3)]);
                b[nt][0] = bb.x; b[nt][1] = bb.y;
            }
#pragma unroll
            for (int i = 0; i < 3; i++) {
                const int abase = sbV + i * SV_I + (warp_t * 16 + (lane >> 2)) * PV
                                + 8 * g + 2 * (lane & 3);
                const uint2 a01 = *reinterpret_cast<const uint2*>(&sV[abase]);
                const uint2 a23 = *reinterpret_cast<const uint2*>(&sV[abase + 8 * PV]);
                uint32_t a[4] = {a01.x, a23.x, a01.y, a23.y};
#pragma unroll
                for (int nt = 0; nt < 4; nt++) mma8(acc[i][nt], a, b[nt]);
            }
        }
        __syncthreads();
    }

    // ---- epilogue: out1 (1o->1o), interleaved layout, vectorized float2
    const float sc = 0.04419417382415922f;  // 1/sqrt(512)
    {
        const int r  = tt0 + warp_t * 16 + (lane >> 2);
        const int wc = w0 + warp_w * 32 + 2 * (lane & 3);
#pragma unroll
        for (int nt = 0; nt < 4; nt++) {
            const int w = wc + nt * 8;
            float* p  = out + (size_t)r * OUTW + 512 + 3 * w;
            float* p2 = p + (size_t)8 * OUTW;
            float2 v;
            v = make_float2(acc[0][nt][0] * sc, acc[1][nt][0] * sc); *reinterpret_cast<float2*>(p + 0) = v;
            v = make_float2(acc[2][nt][0] * sc, acc[0][nt][1] * sc); *reinterpret_cast<float2*>(p + 2) = v;
            v = make_float2(acc[1][nt][1] * sc, acc[2][nt][1] * sc); *reinterpret_cast<float2*>(p + 4) = v;
            v = make_float2(acc[0][nt][2] * sc, acc[1][nt][2] * sc); *reinterpret_cast<float2*>(p2 + 0) = v;
            v = make_float2(acc[2][nt][2] * sc, acc[0][nt][3] * sc); *reinterpret_cast<float2*>(p2 + 2) = v;
            v = make_float2(acc[1][nt][3] * sc, acc[2][nt][3] * sc); *reinterpret_cast<float2*>(p2 + 4) = v;
        }
    }

    // ---- epilogue: out0 (0e->0e), cols [0,512) — sS/sW0 visible via loop barriers
    {
        const float k3 = 0.5773502691896258f;  // 1/sqrt(3)
        const int r  = tid >> 3;
        const int cb = (tid & 7) * 16;
        const float s0 = sS[r * 4 + 0], s1 = sS[r * 4 + 1], s2 = sS[r * 4 + 2];
        float* po = out + (size_t)(tt0 + r) * OUTW + w0 + cb;
#pragma unroll
        for (int jj = 0; jj < 16; jj += 4) {
            float4 v;
            v.x = (s0 * sW0[cb + jj + 0] + s1 * sW0[128 + cb + jj + 0] + s2 * sW0[256 + cb + jj + 0]) * k3;
            v.y = (s0 * sW0[cb + jj + 1] + s1 * sW0[128 + cb + jj + 1] + s2 * sW0[256 + cb + jj + 1]) * k3;
            v.z = (s0 * sW0[cb + jj + 2] + s1 * sW0[128 + cb + jj + 2] + s2 * sW0[256 + cb + jj + 2]) * k3;
            v.w = (s0 * sW0[cb + jj + 3] + s1 * sW0[128 + cb + jj + 3] + s2 * sW0[256 + cb + jj + 3]) * k3;
            *reinterpret_cast<float4*>(po + jj) = v;
        }
    }
}

extern "C" void kernel_launch(void* const* d_in, const int* in_sizes, int n_in,
                              void* d_out, int out_size) {
    const float* V  = nullptr;   // vectors [4,2048,1536] = 12582912
    const float* S  = nullptr;   // scalars [4,2048,3]    = 24576
    const float* W0 = nullptr;   // [3,512]               = 1536
    const float* W1 = nullptr;   // [512,512]             = 262144
    for (int i = 0; i < n_in; i++) {
        switch (in_sizes[i]) {
            case 12582912: V  = (const float*)d_in[i]; break;
            case 24576:    S  = (const float*)d_in[i]; break;
            case 1536:     W0 = (const float*)d_in[i]; break;
            case 262144:   W1 = (const float*)d_in[i]; break;
            default: break;
        }
    }
    float* out = (float*)d_out;

    cudaFuncSetAttribute(fused, cudaFuncAttributeMaxDynamicSharedMemorySize, SMEM_BYTES);
    dim3 grid(MULT / BW, T_TOT / BT);   // (4, 128) = 512 CTAs
    fused<<<grid, NTHR, SMEM_BYTES>>>(V, W1, S, W0, out);
}

// round 4
// speedup vs baseline: 2.9299x; 2.1184x over previous
#include <cuda_runtime.h>
#include <cstdint>
#include <cstddef>

#define T_TOT 8192
#define MULT  512
#define OUTW  8192
#define VROW  1536

#define BT 64
#define BW 128
#define NTHR 512
#define NITER 16

#define PA 100                       // words per A row  (96 data + 4 pad)
#define PB 132                       // words per B row  (128 data + 4 pad)
#define A_STAGE_W (BT*PA)            // 6400 words
#define B_STAGE_W (32*PB)            // 4224 words
#define STAGE_W   (A_STAGE_W + B_STAGE_W)
#define DYN_SMEM  (2*STAGE_W*4)      // 84992 bytes

static __device__ __forceinline__ uint32_t smem_u32(const void* p) {
    uint32_t r;
    asm("{ .reg .u64 t; cvta.to.shared.u64 t, %1; cvt.u32.u64 %0, t; }" : "=r"(r) : "l"(p));
    return r;
}
static __device__ __forceinline__ uint32_t f2tf(float x) {
    uint32_t r; asm("cvt.rna.tf32.f32 %0, %1;" : "=r"(r) : "f"(x)); return r;
}
static __device__ __forceinline__ void cpa16(uint32_t dst, const void* src) {
    asm volatile("cp.async.cg.shared.global [%0], [%1], 16;" :: "r"(dst), "l"(src));
}
static __device__ __forceinline__ void mma8(float* c, const uint32_t* a, const uint32_t* b) {
    asm volatile(
        "mma.sync.aligned.m16n8k8.row.col.f32.tf32.tf32.f32 "
        "{%0,%1,%2,%3},{%4,%5,%6,%7},{%8,%9},{%0,%1,%2,%3};\n"
        : "+f"(c[0]), "+f"(c[1]), "+f"(c[2]), "+f"(c[3])
        : "r"(a[0]), "r"(a[1]), "r"(a[2]), "r"(a[3]),
          "r"(b[0]), "r"(b[1]));
}

__global__ void __launch_bounds__(NTHR, 1)
fused(const float* __restrict__ V, const float* __restrict__ W1,
      const float* __restrict__ S, const float* __restrict__ W0,
      float* __restrict__ out)
{
    extern __shared__ float dsm[];
    __shared__ float sS[192];
    __shared__ float sW0[384];

    const int tid  = threadIdx.x;
    const int lane = tid & 31;
    const int wid  = tid >> 5;
    const int q  = lane >> 2;          // 0..7
    const int rr = lane & 3;           // 0..3
    const int warp_t = wid >> 2;       // 0..3 -> rows warp_t*16
    const int warp_w = wid & 3;        // 0..3 -> cols warp_w*32
    const int bx = blockIdx.x, by = blockIdx.y;
    const int tt0 = by * BT, w0 = bx * BW;

    // small prologue loads (visible after first loop barrier)
    if (tid < 192) sS[tid]  = S[(size_t)tt0 * 3 + tid];
    if (tid < 384) sW0[tid] = W0[(tid >> 7) * 512 + w0 + (tid & 127)];

    // ---- cp.async staging addresses (loop-invariant)
    const uint32_t smem0 = smem_u32(dsm);
    uint32_t aDst[3]; const char* aSrc[3];
#pragma unroll
    for (int s = 0; s < 3; s++) {
        const int c = tid + s * NTHR;          // 0..1535 (64 rows * 24 chunks)
        const int t = c / 24, j = c % 24;
        aDst[s] = smem0 + t * 400 + 16 * j;
        aSrc[s] = (const char*)V + (size_t)(tt0 + t) * VROW * 4 + 16 * j;
    }
    uint32_t bDst[2]; const char* bSrc[2];
#pragma unroll
    for (int s = 0; s < 2; s++) {
        const int c = tid + s * NTHR;          // 0..1023 (32 rows * 32 chunks)
        const int u = c >> 5, j = c & 31;
        bDst[s] = smem0 + A_STAGE_W * 4 + u * 528 + 16 * j;
        bSrc[s] = (const char*)W1 + ((size_t)u * MULT + w0) * 4 + 16 * j;
    }

#define STAGE(K, BUF) do {                                                  \
        const uint32_t off_ = (BUF) * (STAGE_W * 4);                        \
        _Pragma("unroll")                                                   \
        for (int s_ = 0; s_ < 3; s_++)                                      \
            cpa16(aDst[s_] + off_, aSrc[s_] + (size_t)(K) * 384);           \
        _Pragma("unroll")                                                   \
        for (int s_ = 0; s_ < 2; s_++)                                      \
            cpa16(bDst[s_] + off_, bSrc[s_] + (size_t)(K) * 65536);         \
        asm volatile("cp.async.commit_group;" ::: "memory");                \
    } while (0)

    float acc[3][4][4];
#pragma unroll
    for (int i = 0; i < 3; i++)
#pragma unroll
        for (int n = 0; n < 4; n++)
#pragma unroll
            for (int r = 0; r < 4; r++) acc[i][n][r] = 0.f;

    STAGE(0, 0);
    STAGE(1, 1);

    float4* out4 = reinterpret_cast<float4*>(out);
    const float4 zq = make_float4(0.f, 0.f, 0.f, 0.f);

    for (int it = 0; it < NITER; ++it) {
        const int buf = it & 1;
        if (it < NITER - 2) asm volatile("cp.async.wait_group 1;" ::: "memory");
        else                asm volatile("cp.async.wait_group 0;" ::: "memory");
        __syncthreads();

        // ---- stream the exact-zero block (4 rows x 384 quads per iter)
        {
            const int r = 4 * it + (tid >> 7);
            const int c = (tid & 127) * 3;
            float4* zp = out4 + (size_t)(tt0 + r) * 2048 + 512 + 384 * bx + c;
            zp[0] = zq; zp[1] = zq; zp[2] = zq;
        }

        // ---- compute 4 k8-steps from this buffer
        const float* sA = dsm + buf * STAGE_W;
        const float* sB = sA + A_STAGE_W;
        const int arow = (warp_t * 16 + q) * PA;
#pragma unroll
        for (int g = 0; g < 4; g++) {
            uint32_t b[4][2];
            const int brow = (8 * g + rr) * PB;
#pragma unroll
            for (int nt = 0; nt < 4; nt++) {
                const int n = warp_w * 32 + nt * 8 + q;
                b[nt][0] = f2tf(sB[brow + n]);
                b[nt][1] = f2tf(sB[brow + 4 * PB + n]);
            }
#pragma unroll
            for (int i = 0; i < 3; i++) {
                const int a0 = arow + 24 * g + 3 * rr + i;
                uint32_t a[4];
                a[0] = f2tf(sA[a0]);
                a[1] = f2tf(sA[a0 + 8 * PA]);
                a[2] = f2tf(sA[a0 + 12]);
                a[3] = f2tf(sA[a0 + 8 * PA + 12]);
#pragma unroll
                for (int nt = 0; nt < 4; nt++) mma8(acc[i][nt], a, b[nt]);
            }
        }
        __syncthreads();
        if (it < NITER - 2) STAGE(it + 2, buf);
    }

    // ---- epilogue: out1 (1o->1o), interleaved layout, vectorized float2
    const float sc = 0.04419417382415922f;  // 1/sqrt(512)
    {
        const int r  = tt0 + warp_t * 16 + q;
        const int wc = w0 + warp_w * 32 + 2 * rr;
#pragma unroll
        for (int nt = 0; nt < 4; nt++) {
            const int w = wc + nt * 8;
            float* p  = out + (size_t)r * OUTW + 512 + 3 * w;
            float* p2 = p + (size_t)8 * OUTW;
            float2 v;
            v = make_float2(acc[0][nt][0] * sc, acc[1][nt][0] * sc); *reinterpret_cast<float2*>(p + 0) = v;
            v = make_float2(acc[2][nt][0] * sc, acc[0][nt][1] * sc); *reinterpret_cast<float2*>(p + 2) = v;
            v = make_float2(acc[1][nt][1] * sc, acc[2][nt][1] * sc); *reinterpret_cast<float2*>(p + 4) = v;
            v = make_float2(acc[0][nt][2] * sc, acc[1][nt][2] * sc); *reinterpret_cast<float2*>(p2 + 0) = v;
            v = make_float2(acc[2][nt][2] * sc, acc[0][nt][3] * sc); *reinterpret_cast<float2*>(p2 + 2) = v;
            v = make_float2(acc[1][nt][3] * sc, acc[2][nt][3] * sc); *reinterpret_cast<float2*>(p2 + 4) = v;
        }
    }

    // ---- epilogue: out0 (0e->0e), cols [w0, w0+128)
    {
        const float k3 = 0.5773502691896258f;  // 1/sqrt(3)
        const int r  = tid >> 3;
        const int cb = (tid & 7) * 16;
        const float s0 = sS[r * 3 + 0], s1 = sS[r * 3 + 1], s2 = sS[r * 3 + 2];
        float* po = out + (size_t)(tt0 + r) * OUTW + w0 + cb;
#pragma unroll
        for (int jj = 0; jj < 16; jj += 4) {
            float4 v;
            v.x = (s0 * sW0[cb + jj + 0] + s1 * sW0[128 + cb + jj + 0] + s2 * sW0[256 + cb + jj + 0]) * k3;
            v.y = (s0 * sW0[cb + jj + 1] + s1 * sW0[128 + cb + jj + 1] + s2 * sW0[256 + cb + jj + 1]) * k3;
            v.z = (s0 * sW0[cb + jj + 2] + s1 * sW0[128 + cb + jj + 2] + s2 * sW0[256 + cb + jj + 2]) * k3;
            v.w = (s0 * sW0[cb + jj + 3] + s1 * sW0[128 + cb + jj + 3] + s2 * sW0[256 + cb + jj + 3]) * k3;
            *reinterpret_cast<float4*>(po + jj) = v;
        }
    }
}

extern "C" void kernel_launch(void* const* d_in, const int* in_sizes, int n_in,
                              void* d_out, int out_size) {
    const float* V  = nullptr;   // vectors [4,2048,1536] = 12582912
    const float* S  = nullptr;   // scalars [4,2048,3]    = 24576
    const float* W0 = nullptr;   // [3,512]               = 1536
    const float* W1 = nullptr;   // [512,512]             = 262144
    for (int i = 0; i < n_in; i++) {
        switch (in_sizes[i]) {
            case 12582912: V  = (const float*)d_in[i]; break;
            case 24576:    S  = (const float*)d_in[i]; break;
            case 1536:     W0 = (const float*)d_in[i]; break;
            case 262144:   W1 = (const float*)d_in[i]; break;
            default: break;
        }
    }
    float* out = (float*)d_out;

    cudaFuncSetAttribute(fused, cudaFuncAttributeMaxDynamicSharedMemorySize, DYN_SMEM);
    dim3 grid(MULT / BW, T_TOT / BT);   // (4, 128) = 512 CTAs
    fused<<<grid, NTHR, DYN_SMEM>>>(V, W1, S, W0, out);
}